// round 16
// baseline (speedup 1.0000x reference)
#include <cuda_runtime.h>
#include <cstdint>

// ---------------------------------------------------------------------------
// QNNClassifier fused single-kernel — cp.async staged streaming.
//
//   ev = (1, cos x0, sin x0)^T K (1, cos x1, sin x1)
//
// Each block stages its 16KB input slice (2048 samples) into smem via
// cp.async (LDGSTS, 16B, SW128-swizzled) — no registers consumed, the whole
// input is in flight chip-wide at kernel start. Warp 0 computes the 9
// batch-shared coefficients K (zero-shuffle closed form) between the
// cp.async commit and wait, so the prologue costs nothing. Post-barrier:
// swizzled LDS.128 reads, trig, coalesced STG.128. Single wave (1024 blocks).
// ---------------------------------------------------------------------------

struct Cx { float re, im; };
__device__ __forceinline__ Cx cmul(Cx a, Cx b) {
    return { a.re * b.re - a.im * b.im, a.re * b.im + a.im * b.re };
}

__device__ __forceinline__ uint32_t swz128(uint32_t byte_off) {
    return byte_off ^ ((byte_off >> 3) & 0x70);
}

__device__ __forceinline__ uint32_t smem_u32(const void* p) {
    return (uint32_t)__cvta_generic_to_shared(p);
}

// Warp 0 only. Lane L=4i+j computes U[i][j] in closed form (no shuffles).
__device__ __forceinline__ void warp0_compute_K(const float* __restrict__ qp,
                                                const float* __restrict__ fc_w,
                                                const float* __restrict__ fc_b,
                                                float* sU, float* sA, float* sK) {
    int L = threadIdx.x;
    int i = (L >> 2) & 3, j = L & 3;

    if (L < 16) {
        float ph0 = qp[0], th0 = qp[1], om0 = qp[2];
        float ph1 = qp[3], th1 = qp[4], om1 = qp[5];

        float s0, c0; __sincosf(0.5f * th0, &s0, &c0);
        float sp0, cp0, sm0, cm0;
        __sincosf(-0.5f * (ph0 + om0), &sp0, &cp0);
        __sincosf( 0.5f * (ph0 - om0), &sm0, &cm0);
        Cx a00 = {  cp0 * c0,  sp0 * c0 };
        Cx a01 = { -cm0 * s0, -sm0 * s0 };
        Cx a10 = {  cm0 * s0, -sm0 * s0 };
        Cx a11 = {  cp0 * c0, -sp0 * c0 };

        float s1, c1; __sincosf(0.5f * th1, &s1, &c1);
        float sp1, cp1, sm1, cm1;
        __sincosf(-0.5f * (ph1 + om1), &sp1, &cp1);
        __sincosf( 0.5f * (ph1 - om1), &sm1, &cm1);
        Cx b00 = {  cp1 * c1,  sp1 * c1 };
        Cx b01 = { -cm1 * s1, -sm1 * s1 };
        Cx b10 = {  cm1 * s1, -sm1 * s1 };
        Cx b11 = {  cp1 * c1, -sp1 * c1 };

        int jh = j >> 1, jl = j & 1;
        Cx a_cj0 = jh ? a01 : a00;
        Cx a_cj1 = jh ? a11 : a10;
        Cx b_cj0 = jl ? b01 : b00;
        Cx b_cj1 = jl ? b11 : b10;

        // g1[k] = G1[q[k]][j], q = {0,2,3,1}
        Cx g1_0 = cmul(a_cj0, b_cj0);
        Cx g1_1 = cmul(a_cj1, b_cj0);
        Cx g1_2 = cmul(a_cj1, b_cj1);
        Cx g1_3 = cmul(a_cj0, b_cj1);

        float ph2 = qp[6], th2 = qp[7], om2 = qp[8];
        float ph3 = qp[9], th3 = qp[10], om3 = qp[11];

        float s2, c2; __sincosf(0.5f * th2, &s2, &c2);
        float sp2, cp2, sm2, cm2;
        __sincosf(-0.5f * (ph2 + om2), &sp2, &cp2);
        __sincosf( 0.5f * (ph2 - om2), &sm2, &cm2);
        Cx d00 = {  cp2 * c2,  sp2 * c2 };
        Cx d01 = { -cm2 * s2, -sm2 * s2 };
        Cx d10 = {  cm2 * s2, -sm2 * s2 };
        Cx d11 = {  cp2 * c2, -sp2 * c2 };

        float s3, c3; __sincosf(0.5f * th3, &s3, &c3);
        float sp3, cp3, sm3, cm3;
        __sincosf(-0.5f * (ph3 + om3), &sp3, &cp3);
        __sincosf( 0.5f * (ph3 - om3), &sm3, &cm3);
        Cx e00 = {  cp3 * c3,  sp3 * c3 };
        Cx e01 = { -cm3 * s3, -sm3 * s3 };
        Cx e10 = {  cm3 * s3, -sm3 * s3 };
        Cx e11 = {  cp3 * c3, -sp3 * c3 };

        int a = (0x78 >> (2 * i)) & 3;   // q = {0,2,3,1}
        int ah = a >> 1, al = a & 1;
        Cx d_r0 = ah ? d10 : d00;
        Cx d_r1 = ah ? d11 : d01;
        Cx e_r0 = al ? e10 : e00;
        Cx e_r1 = al ? e11 : e01;

        Cx U = { 0.f, 0.f };
        Cx g2;
        g2 = cmul(d_r0, e_r0);  U.re += g2.re * g1_0.re - g2.im * g1_0.im;
                                U.im += g2.re * g1_0.im + g2.im * g1_0.re;
        g2 = cmul(d_r0, e_r1);  U.re += g2.re * g1_1.re - g2.im * g1_1.im;
                                U.im += g2.re * g1_1.im + g2.im * g1_1.re;
        g2 = cmul(d_r1, e_r0);  U.re += g2.re * g1_2.re - g2.im * g1_2.im;
                                U.im += g2.re * g1_2.im + g2.im * g1_2.re;
        g2 = cmul(d_r1, e_r1);  U.re += g2.re * g1_3.re - g2.im * g1_3.im;
                                U.im += g2.re * g1_3.im + g2.im * g1_3.re;

        sU[2 * L + 0] = U.re;
        sU[2 * L + 1] = U.im;
    }
    __syncwarp();

    if (L < 16) {
        float acc = 0.f;
        #pragma unroll
        for (int k = 0; k < 4; k++) {
            float ire = sU[2 * (4 * k + i) + 0];
            float iim = sU[2 * (4 * k + i) + 1];
            float jre = sU[2 * (4 * k + j) + 0];
            float jim = sU[2 * (4 * k + j) + 1];
            float dot = ire * jre + iim * jim;
            acc += (k < 2) ? dot : -dot;
        }
        sA[L] = acc;
    }
    __syncwarp();

    if (L == 0) {
        float w = fc_w[0];
        float A00 = w * sA[0],  A01 = w * sA[1],  A02 = w * sA[2],  A03 = w * sA[3];
        float A11 = w * sA[5],  A12 = w * sA[6],  A13 = w * sA[7];
        float A22 = w * sA[10], A23 = w * sA[11], A33 = w * sA[15];
        sK[0] = 0.25f * (A00 + A11 + A22 + A33) + fc_b[0];
        sK[1] = 0.25f * (A00 - A11 + A22 - A33);   // C1
        sK[2] = 0.50f * (A01 + A23);               // S1
        sK[3] = 0.25f * (A00 + A11 - A22 - A33);   // C0
        sK[4] = 0.25f * (A00 - A11 - A22 + A33);   // C0C1
        sK[5] = 0.50f * (A01 - A23);               // C0S1
        sK[6] = 0.50f * (A02 + A13);               // S0
        sK[7] = 0.50f * (A02 - A13);               // S0C1
        sK[8] = 0.50f * (A03 + A12);               // S0S1
    }
}

// Block = 256 threads, 2048 samples (16KB in, 8KB out). 8 samples/thread.
__global__ void __launch_bounds__(256)
qnn_fused_kernel(const float* __restrict__ qp,
                 const float* __restrict__ fc_w,
                 const float* __restrict__ fc_b,
                 const float4* __restrict__ x4,
                 float4* __restrict__ out4,
                 int n_in4, int n_out4) {
    __shared__ __align__(128) char sX[16384];   // 1024 x 16B chunks, SW128 swizzled
    __shared__ float sU[32];
    __shared__ float sA[16];
    __shared__ float sK[9];

    int tid = threadIdx.x;
    unsigned b = blockIdx.x;
    unsigned cbase = b * 1024u;
    uint32_t sx = smem_u32(sX);

    // Stage the block's input slice: 4 x 16B cp.async per thread, coalesced.
    #pragma unroll
    for (int k = 0; k < 4; k++) {
        unsigned c = (unsigned)(k * 256 + tid);
        unsigned gc = cbase + c;
        if (gc < (unsigned)n_in4) {
            uint32_t dst = sx + swz128(c * 16u);
            const float4* src = x4 + gc;
            asm volatile("cp.async.cg.shared.global [%0], [%1], 16;"
                         :: "r"(dst), "l"(src) : "memory");
        }
    }
    asm volatile("cp.async.commit_group;" ::: "memory");

    // K prologue runs while the copies are in flight.
    if (tid < 32) {
        warp0_compute_K(qp, fc_w, fc_b, sU, sA, sK);
    }

    asm volatile("cp.async.wait_group 0;" ::: "memory");
    __syncthreads();

    float k00 = sK[0], k01 = sK[1], k02 = sK[2];
    float k10 = sK[3], k11 = sK[4], k12 = sK[5];
    float k20 = sK[6], k21 = sK[7], k22 = sK[8];

    // Each thread produces 2 output float4s (8 samples).
    #pragma unroll
    for (int r = 0; r < 2; r++) {
        unsigned o = (unsigned)(r * 256 + tid);     // block-local output float4
        unsigned go = b * 512u + o;
        if (go < (unsigned)n_out4) {
            // Output float4 o covers samples 4o..4o+3 = input chunks 2o, 2o+1.
            const float4* pa = (const float4*)(sX + swz128(o * 32u));
            const float4* pb = (const float4*)(sX + swz128(o * 32u + 16u));
            float4 va = *pa;
            float4 vb = *pb;

            float xs[8] = { va.x, va.y, va.z, va.w, vb.x, vb.y, vb.z, vb.w };
            float res[4];
            #pragma unroll
            for (int s = 0; s < 4; s++) {
                float C0, S0, C1, S1;
                __sincosf(xs[2 * s + 0], &S0, &C0);
                __sincosf(xs[2 * s + 1], &S1, &C1);
                float row0 = k00 + k01 * C1 + k02 * S1;
                float row1 = k10 + k11 * C1 + k12 * S1;
                float row2 = k20 + k21 * C1 + k22 * S1;
                res[s] = row0 + C0 * row1 + S0 * row2;
            }
            out4[go] = make_float4(res[0], res[1], res[2], res[3]);
        }
    }
}

extern "C" void kernel_launch(void* const* d_in, const int* in_sizes, int n_in,
                              void* d_out, int out_size) {
    const float* x    = (const float*)d_in[0];   // [B, 2]
    const float* qp   = (const float*)d_in[1];   // [2, 2, 3]
    const float* fc_w = (const float*)d_in[2];   // [1, 1]
    const float* fc_b = (const float*)d_in[3];   // [1]

    int n_in4  = out_size / 2;   // input float4 count  (B*2 floats / 4)
    int n_out4 = out_size / 4;   // output float4 count
    int blocks = (out_size + 2047) / 2048;       // 1024 for B=2M

    qnn_fused_kernel<<<blocks, 256>>>(qp, fc_w, fc_b,
                                      (const float4*)x, (float4*)d_out,
                                      n_in4, n_out4);
    (void)n_in; (void)in_sizes;
}

// round 17
// speedup vs baseline: 1.0295x; 1.0295x over previous
#include <cuda_runtime.h>

// ---------------------------------------------------------------------------
// QNNClassifier — persistent single-wave kernel with register-double-buffered
// grid-stride main loop (software pipelining: next tile's loads fly during
// current tile's trig/FMA burst, so memory and compute pipes overlap instead
// of phase-alternating).
//
//   ev = (1, cos x0, sin x0)^T K (1, cos x1, sin x1)
//
// K (9 coefficients, fc_w/fc_b folded) built once per block by warp 0 via the
// zero-shuffle closed form (lane L=4i+j computes U[i][j] directly); amortized
// over the block's 3-4 tiles and hidden under the first prefetch.
// ---------------------------------------------------------------------------

struct Cx { float re, im; };
__device__ __forceinline__ Cx cmul(Cx a, Cx b) {
    return { a.re * b.re - a.im * b.im, a.re * b.im + a.im * b.re };
}

// Warp 0 only. Lane L=4i+j computes U[i][j] in closed form (no shuffles).
__device__ __forceinline__ void warp0_compute_K(const float* __restrict__ qp,
                                                const float* __restrict__ fc_w,
                                                const float* __restrict__ fc_b,
                                                float* sU, float* sA, float* sK) {
    int L = threadIdx.x;
    int i = (L >> 2) & 3, j = L & 3;

    if (L < 16) {
        float ph0 = qp[0], th0 = qp[1], om0 = qp[2];
        float ph1 = qp[3], th1 = qp[4], om1 = qp[5];

        float s0, c0; __sincosf(0.5f * th0, &s0, &c0);
        float sp0, cp0, sm0, cm0;
        __sincosf(-0.5f * (ph0 + om0), &sp0, &cp0);
        __sincosf( 0.5f * (ph0 - om0), &sm0, &cm0);
        Cx a00 = {  cp0 * c0,  sp0 * c0 };
        Cx a01 = { -cm0 * s0, -sm0 * s0 };
        Cx a10 = {  cm0 * s0, -sm0 * s0 };
        Cx a11 = {  cp0 * c0, -sp0 * c0 };

        float s1, c1; __sincosf(0.5f * th1, &s1, &c1);
        float sp1, cp1, sm1, cm1;
        __sincosf(-0.5f * (ph1 + om1), &sp1, &cp1);
        __sincosf( 0.5f * (ph1 - om1), &sm1, &cm1);
        Cx b00 = {  cp1 * c1,  sp1 * c1 };
        Cx b01 = { -cm1 * s1, -sm1 * s1 };
        Cx b10 = {  cm1 * s1, -sm1 * s1 };
        Cx b11 = {  cp1 * c1, -sp1 * c1 };

        int jh = j >> 1, jl = j & 1;
        Cx a_cj0 = jh ? a01 : a00;
        Cx a_cj1 = jh ? a11 : a10;
        Cx b_cj0 = jl ? b01 : b00;
        Cx b_cj1 = jl ? b11 : b10;

        // g1[k] = G1[q[k]][j], q = {0,2,3,1}
        Cx g1_0 = cmul(a_cj0, b_cj0);
        Cx g1_1 = cmul(a_cj1, b_cj0);
        Cx g1_2 = cmul(a_cj1, b_cj1);
        Cx g1_3 = cmul(a_cj0, b_cj1);

        float ph2 = qp[6], th2 = qp[7], om2 = qp[8];
        float ph3 = qp[9], th3 = qp[10], om3 = qp[11];

        float s2, c2; __sincosf(0.5f * th2, &s2, &c2);
        float sp2, cp2, sm2, cm2;
        __sincosf(-0.5f * (ph2 + om2), &sp2, &cp2);
        __sincosf( 0.5f * (ph2 - om2), &sm2, &cm2);
        Cx d00 = {  cp2 * c2,  sp2 * c2 };
        Cx d01 = { -cm2 * s2, -sm2 * s2 };
        Cx d10 = {  cm2 * s2, -sm2 * s2 };
        Cx d11 = {  cp2 * c2, -sp2 * c2 };

        float s3, c3; __sincosf(0.5f * th3, &s3, &c3);
        float sp3, cp3, sm3, cm3;
        __sincosf(-0.5f * (ph3 + om3), &sp3, &cp3);
        __sincosf( 0.5f * (ph3 - om3), &sm3, &cm3);
        Cx e00 = {  cp3 * c3,  sp3 * c3 };
        Cx e01 = { -cm3 * s3, -sm3 * s3 };
        Cx e10 = {  cm3 * s3, -sm3 * s3 };
        Cx e11 = {  cp3 * c3, -sp3 * c3 };

        int a = (0x78 >> (2 * i)) & 3;   // q = {0,2,3,1}
        int ah = a >> 1, al = a & 1;
        Cx d_r0 = ah ? d10 : d00;
        Cx d_r1 = ah ? d11 : d01;
        Cx e_r0 = al ? e10 : e00;
        Cx e_r1 = al ? e11 : e01;

        Cx U = { 0.f, 0.f };
        Cx g2;
        g2 = cmul(d_r0, e_r0);  U.re += g2.re * g1_0.re - g2.im * g1_0.im;
                                U.im += g2.re * g1_0.im + g2.im * g1_0.re;
        g2 = cmul(d_r0, e_r1);  U.re += g2.re * g1_1.re - g2.im * g1_1.im;
                                U.im += g2.re * g1_1.im + g2.im * g1_1.re;
        g2 = cmul(d_r1, e_r0);  U.re += g2.re * g1_2.re - g2.im * g1_2.im;
                                U.im += g2.re * g1_2.im + g2.im * g1_2.re;
        g2 = cmul(d_r1, e_r1);  U.re += g2.re * g1_3.re - g2.im * g1_3.im;
                                U.im += g2.re * g1_3.im + g2.im * g1_3.re;

        sU[2 * L + 0] = U.re;
        sU[2 * L + 1] = U.im;
    }
    __syncwarp();

    if (L < 16) {
        float acc = 0.f;
        #pragma unroll
        for (int k = 0; k < 4; k++) {
            float ire = sU[2 * (4 * k + i) + 0];
            float iim = sU[2 * (4 * k + i) + 1];
            float jre = sU[2 * (4 * k + j) + 0];
            float jim = sU[2 * (4 * k + j) + 1];
            float dot = ire * jre + iim * jim;
            acc += (k < 2) ? dot : -dot;
        }
        sA[L] = acc;
    }
    __syncwarp();

    if (L == 0) {
        float w = fc_w[0];
        float A00 = w * sA[0],  A01 = w * sA[1],  A02 = w * sA[2],  A03 = w * sA[3];
        float A11 = w * sA[5],  A12 = w * sA[6],  A13 = w * sA[7];
        float A22 = w * sA[10], A23 = w * sA[11], A33 = w * sA[15];
        sK[0] = 0.25f * (A00 + A11 + A22 + A33) + fc_b[0];
        sK[1] = 0.25f * (A00 - A11 + A22 - A33);   // C1
        sK[2] = 0.50f * (A01 + A23);               // S1
        sK[3] = 0.25f * (A00 + A11 - A22 - A33);   // C0
        sK[4] = 0.25f * (A00 - A11 - A22 + A33);   // C0C1
        sK[5] = 0.50f * (A01 - A23);               // C0S1
        sK[6] = 0.50f * (A02 + A13);               // S0
        sK[7] = 0.50f * (A02 - A13);               // S0C1
        sK[8] = 0.50f * (A03 + A12);               // S0S1
    }
}

__device__ __forceinline__ float4 eval_tile(float k00, float k01, float k02,
                                            float k10, float k11, float k12,
                                            float k20, float k21, float k22,
                                            const float4& xa, const float4& xb) {
    float xs[8] = { xa.x, xa.y, xa.z, xa.w, xb.x, xb.y, xb.z, xb.w };
    float res[4];
    #pragma unroll
    for (int s = 0; s < 4; s++) {
        float C0, S0, C1, S1;
        __sincosf(xs[2 * s + 0], &S0, &C0);
        __sincosf(xs[2 * s + 1], &S1, &C1);
        float row0 = k00 + k01 * C1 + k02 * S1;
        float row1 = k10 + k11 * C1 + k12 * S1;
        float row2 = k20 + k21 * C1 + k22 * S1;
        res[s] = row0 + C0 * row1 + S0 * row2;
    }
    return make_float4(res[0], res[1], res[2], res[3]);
}

// Persistent single wave: grid-stride loop, register double buffering.
__global__ void __launch_bounds__(256)
qnn_persistent_kernel(const float* __restrict__ qp,
                      const float* __restrict__ fc_w,
                      const float* __restrict__ fc_b,
                      const float4* __restrict__ x4,
                      float4* __restrict__ out4,
                      int nquad) {
    __shared__ float sU[32];
    __shared__ float sA[16];
    __shared__ float sK[9];

    unsigned stride = gridDim.x * 256u;
    unsigned t = blockIdx.x * 256u + threadIdx.x;

    // Prefetch tile 0 immediately (in flight during the K prologue).
    float4 xa, xb;
    bool have = t < (unsigned)nquad;
    if (have) {
        xa = x4[2u * t + 0];
        xb = x4[2u * t + 1];
    }

    if (threadIdx.x < 32) {
        warp0_compute_K(qp, fc_w, fc_b, sU, sA, sK);
    }
    __syncthreads();

    float k00 = sK[0], k01 = sK[1], k02 = sK[2];
    float k10 = sK[3], k11 = sK[4], k12 = sK[5];
    float k20 = sK[6], k21 = sK[7], k22 = sK[8];

    // Software-pipelined grid-stride loop: prefetch (t+stride) before
    // computing tile t, so the next loads fly under the current trig burst.
    while (have) {
        unsigned tn = t + stride;
        bool have_n = tn < (unsigned)nquad;
        float4 xan, xbn;
        if (have_n) {
            xan = x4[2u * tn + 0];
            xbn = x4[2u * tn + 1];
        }

        out4[t] = eval_tile(k00, k01, k02, k10, k11, k12, k20, k21, k22, xa, xb);

        xa = xan; xb = xbn;
        t = tn;
        have = have_n;
    }
}

extern "C" void kernel_launch(void* const* d_in, const int* in_sizes, int n_in,
                              void* d_out, int out_size) {
    const float* x    = (const float*)d_in[0];   // [B, 2]
    const float* qp   = (const float*)d_in[1];   // [2, 2, 3]
    const float* fc_w = (const float*)d_in[2];   // [1, 1]
    const float* fc_b = (const float*)d_in[3];   // [1]

    int nquad = out_size / 4;          // float4 outputs (512K for B=2M)
    int threads = 256;
    int blocks = 592;                  // 148 SMs x 4 blocks — one resident wave

    qnn_persistent_kernel<<<blocks, threads>>>(qp, fc_w, fc_b,
                                               (const float4*)x, (float4*)d_out,
                                               nquad);
    (void)n_in; (void)in_sizes;
}